// round 17
// baseline (speedup 1.0000x reference)
#include <cuda_runtime.h>
#include <cuda_bf16.h>
#include <cstdint>

#define TILE    128
#define TSTEPS  10
#define HID     50
#define THREADS 512
#define NCTA    1024            // 131072 / 128
#define AST     120             // bf16 per A row (60 words; 60%8==4 -> conflict-free afrag)
#define NKT     7               // K = 112: x @ k0..55, h @ k56..111
#define LSCR    (TSTEPS * HID * TILE)   // 64000 floats per CTA, layout [t][j][m]

__device__ float g_scr[(size_t)NCTA * LSCR];

#define WSM_U2     (25 * NKT * 32)        // 5600 uint2 = 44800 B
#define BIAS_OFF   44800
#define A0_OFF     45600
#define ABUF_B     (TILE * AST * 2)       // 30720 B per buffer
#define SMEM_TOTAL (A0_OFF + 2 * ABUF_B)  // 107040 B  (x2 CTA = 214 KB <= 228 KB)

__device__ __forceinline__ float sigmf(float v) {          // dense head only
    return __fdividef(1.f, 1.f + __expf(-v));
}
// FMA-pipe reciprocal: bit-trick seed + 2 Newton steps, rel err ~1.3e-5, no MUFU
__device__ __forceinline__ float frcp(float y) {
    float r = __uint_as_float(0x7EF311C3u - __float_as_uint(y));
    r = r * (2.f - y * r);
    r = r * (2.f - y * r);
    return r;
}
__device__ __forceinline__ uint32_t pack_bf2(float lo, float hi) {
    __nv_bfloat162 p = __floats2bfloat162_rn(lo, hi);      // .x = lo = lower 16 bits
    return *reinterpret_cast<uint32_t*>(&p);
}
__device__ __forceinline__ void mma16(float (&d)[4], const uint32_t (&a)[4],
                                      uint32_t b0, uint32_t b1) {
    asm volatile("mma.sync.aligned.m16n8k16.row.col.f32.bf16.bf16.f32 "
                 "{%0,%1,%2,%3}, {%4,%5,%6,%7}, {%8,%9}, {%0,%1,%2,%3};\n"
                 : "+f"(d[0]), "+f"(d[1]), "+f"(d[2]), "+f"(d[3])
                 : "r"(a[0]), "r"(a[1]), "r"(a[2]), "r"(a[3]), "r"(b0), "r"(b1));
}

// K=112 stack: k 0..55 = x rows (Fin used), k 56..111 = h rows (50 used)
__device__ __forceinline__ float fetchWU(int k, int sc, const float* W, const float* U, int Fin) {
    if (k < 56) return (k < Fin) ? W[k * 200 + sc] : 0.f;
    int ku = k - 56;
    return (ku < HID) ? U[ku * 200 + sc] : 0.f;
}

// weights pre-permuted into m16n8k16 b-frag order (uint2 per (nt,kt,lane)),
// gate cols permuted col'=4j+q. Fills permuted bias; zeroes BOTH A buffers.
__device__ __forceinline__ void fill_layer_weights(char* smem, const float* __restrict__ W,
                                                   const float* __restrict__ U,
                                                   const float* __restrict__ b,
                                                   int Fin, int tid)
{
    uint2*    wsm   = reinterpret_cast<uint2*>(smem);
    float*    biasp = reinterpret_cast<float*>(smem + BIAS_OFF);
    uint32_t* Az    = reinterpret_cast<uint32_t*>(smem + A0_OFF);
    for (int idx = tid; idx < WSM_U2; idx += THREADS) {
        int nt   = idx / (NKT * 32);
        int rem  = idx - nt * (NKT * 32);
        int kt   = rem >> 5, lane = rem & 31;
        int colp = nt * 8 + (lane >> 2);
        int sc   = (colp & 3) * HID + (colp >> 2);      // original col q*50+j
        int kb   = kt * 16 + (lane & 3) * 2;
        float v0 = fetchWU(kb,     sc, W, U, Fin);
        float v1 = fetchWU(kb + 1, sc, W, U, Fin);
        float v2 = fetchWU(kb + 8, sc, W, U, Fin);
        float v3 = fetchWU(kb + 9, sc, W, U, Fin);
        wsm[idx] = make_uint2(pack_bf2(v0, v1), pack_bf2(v2, v3));
    }
    for (int c = tid; c < 200; c += THREADS)
        biasp[c] = b[(c & 3) * HID + (c >> 2)];
    for (int idx = tid; idx < 2 * TILE * (AST / 2); idx += THREADS)
        Az[idx] = 0u;                                    // zero both buffers (pads + h0)
}

template<bool L0, bool LAST>
__device__ __forceinline__ void run_layer(char* smem, const float* __restrict__ xsrc,
                                          float* __restrict__ scr, int tid)
{
    const uint2* wsm   = reinterpret_cast<const uint2*>(smem);
    const float* biasp = reinterpret_cast<const float*>(smem + BIAS_OFF);
    __nv_bfloat16* buf0 = reinterpret_cast<__nv_bfloat16*>(smem + A0_OFF);
    __nv_bfloat16* buf1 = reinterpret_cast<__nv_bfloat16*>(smem + A0_OFF + ABUF_B);

    const int lane = tid & 31, wrp = tid >> 5;
    const int g = lane >> 2, lam = lane & 3;
    const int mw = wrp >> 1, ng = wrp & 1;        // 8 M-tiles x 2 N-halves
    const int row0  = mw * 16 + g;
    const int ntbeg = ng ? 13 : 0;
    const int ntend = ng ? 25 : 13;
    const bool hi   = lam & 1;
    const int rowE  = row0 + (hi ? 8 : 0);

    float cst[13];
#pragma unroll
    for (int i = 0; i < 13; ++i) cst[i] = 0.f;

    __syncthreads();                               // weights + buffer-zero done

    for (int t = 0; t < TSTEPS; ++t) {
        __nv_bfloat16* Ac = (t & 1) ? buf1 : buf0;     // current-step source
        __nv_bfloat16* An = (t & 1) ? buf0 : buf1;     // next-step source (h dest)

        // ---- fill input cols of Ac (x for L0, prev-layer h for L1..3) ----
        if (L0) {
            for (int idx = tid; idx < TILE * 8; idx += THREADS) {
                int m = idx >> 3, f = idx & 7;
                if (f < 5)
                    Ac[m * AST + f] = __float2bfloat16_rn(xsrc[m * 50 + t * 5 + f]);
            }
        } else {
            const float* sp = scr + t * (HID * TILE);
            for (int idx = tid; idx < TILE * HID; idx += THREADS) {
                int j = idx >> 7, m = idx & 127;
                Ac[m * AST + j] = __float2bfloat16_rn(sp[j * TILE + m]);
            }
        }
        __syncthreads();      // the ONLY per-step barrier: fill + prior epilogue-h visible;
                              // also proves all hoist-reads of An (step t-1) completed

        // ---- hoist a-fragments (L0: kt 1,2 are zero x-pad) ----
        uint32_t af[NKT][4];
#pragma unroll
        for (int kt = 0; kt < NKT; ++kt) {
            if (L0 && (kt == 1 || kt == 2)) continue;
            const __nv_bfloat16* ap = Ac + kt * 16 + lam * 2;
            af[kt][0] = *reinterpret_cast<const uint32_t*>(ap + row0 * AST);
            af[kt][1] = *reinterpret_cast<const uint32_t*>(ap + (row0 + 8) * AST);
            af[kt][2] = *reinterpret_cast<const uint32_t*>(ap + row0 * AST + 8);
            af[kt][3] = *reinterpret_cast<const uint32_t*>(ap + (row0 + 8) * AST + 8);
        }

        for (int nt = ntbeg; nt < ntend; ++nt) {
            float2 bv = *reinterpret_cast<const float2*>(&biasp[nt * 8 + lam * 2]);
            float accA[4] = {bv.x, bv.y, bv.x, bv.y};
            float accB[4] = {0.f, 0.f, 0.f, 0.f};
            const uint2* wp = wsm + nt * (NKT * 32) + lane;
#pragma unroll
            for (int kt = 0; kt < NKT; ++kt) {
                if (L0 && (kt == 1 || kt == 2)) continue;
                uint2 bb = wp[kt * 32];
                if (kt & 1) mma16(accB, af[kt], bb.x, bb.y);
                else        mma16(accA, af[kt], bb.x, bb.y);
            }
            float a0 = accA[0] + accB[0], a1 = accA[1] + accB[1];
            float a2 = accA[2] + accB[2], a3 = accA[3] + accB[3];
            // pair-exchange: each lane ends owning one (row, unit) with all 4 gates
            float p0 = __shfl_xor_sync(0xffffffffu, a0, 1);
            float p1 = __shfl_xor_sync(0xffffffffu, a1, 1);
            float p2 = __shfl_xor_sync(0xffffffffu, a2, 1);
            float p3 = __shfl_xor_sync(0xffffffffu, a3, 1);
            float zi = hi ? p2 : a0;
            float zf = hi ? p3 : a1;
            float zg = hi ? a2 : p0;
            float zo = hi ? a3 : p1;

            // ---- 5-MUFU gate math (EX2 only; reciprocals on FMA pipe) ----
            zi = fmaxf(zi, -30.f);
            zf = fmaxf(zf, -30.f);
            zo = fmaxf(zo, -30.f);
            zg = fminf(fmaxf(zg, -12.f), 12.f);
            float ef = __expf(-zf);
            float ei = __expf(-zi);
            float eg = __expf(2.f * zg);
            float fg = frcp(1.f + ef);                              // sigmoid(zf)
            float ig = (eg - 1.f) * frcp((1.f + ei) * (eg + 1.f));  // sigm(zi)*tanh(zg)
            float c  = fmaf(fg, cst[nt - ntbeg], ig);
            cst[nt - ntbeg] = c;
            float cc = fminf(fmaxf(c, -12.f), 12.f);
            float eo = __expf(-zo);
            float ec = __expf(2.f * cc);
            float h  = (ec - 1.f) * frcp((1.f + eo) * (ec + 1.f));  // sigm(zo)*tanh(c)

            int unit = nt * 2 + (lam >> 1);
            if (LAST) {
                if (t == TSTEPS - 1) scr[(t * HID + unit) * TILE + rowE] = h;  // fp32 for dense
                else                 An[rowE * AST + 56 + unit] = __float2bfloat16_rn(h);
            } else {
                An[rowE * AST + 56 + unit] = __float2bfloat16_rn(h);
                scr[(t * HID + unit) * TILE + rowE] = h;
            }
        }
    }
}

__global__ void __launch_bounds__(THREADS, 2)
lstm_fused(const float* __restrict__ x,
           const float* __restrict__ W0, const float* __restrict__ U0, const float* __restrict__ B0,
           const float* __restrict__ W1, const float* __restrict__ U1, const float* __restrict__ B1,
           const float* __restrict__ W2, const float* __restrict__ U2, const float* __restrict__ B2,
           const float* __restrict__ W3, const float* __restrict__ U3, const float* __restrict__ B3,
           const float* __restrict__ Wd1, const float* __restrict__ bd1,
           const float* __restrict__ Wd2, const float* __restrict__ bd2,
           float* __restrict__ out)
{
    extern __shared__ char smem[];
    const int tid = threadIdx.x;
    const int cta = blockIdx.x;
    float* scr = g_scr + (size_t)cta * LSCR;

    fill_layer_weights(smem, W0, U0, B0, 5, tid);
    run_layer<true,  false>(smem, x + (size_t)cta * TILE * 50, scr, tid);
    __syncthreads();
    fill_layer_weights(smem, W1, U1, B1, HID, tid);
    run_layer<false, false>(smem, nullptr, scr, tid);
    __syncthreads();
    fill_layer_weights(smem, W2, U2, B2, HID, tid);
    run_layer<false, false>(smem, nullptr, scr, tid);
    __syncthreads();
    fill_layer_weights(smem, W3, U3, B3, HID, tid);
    run_layer<false, true >(smem, nullptr, scr, tid);
    __syncthreads();

    // fused dense head: out = sigmoid((h @ Wd1 + bd1) @ Wd2 + bd2)
    float* dw = reinterpret_cast<float*>(smem);          // reuse weight region
    for (int idx = tid; idx < 2500; idx += THREADS)
        dw[idx] = Wd1[(idx % 50) * 50 + idx / 50];       // dw[j2*50+j] = Wd1[j][j2]
    if (tid < 50) { dw[2500 + tid] = bd1[tid]; dw[2550 + tid] = Wd2[tid]; }
    if (tid == 0)  dw[2600] = bd2[0];
    __syncthreads();

    if (tid < TILE) {
        const float* hp = scr + 9 * (HID * TILE) + tid;  // layer-4 last h (fp32, [unit][m])
        float h[HID];
#pragma unroll
        for (int j = 0; j < HID; ++j) h[j] = hp[j * TILE];
        float acc2 = dw[2600];
        for (int j2 = 0; j2 < HID; ++j2) {
            float a = dw[2500 + j2];
#pragma unroll
            for (int j = 0; j < HID; ++j) a += h[j] * dw[j2 * 50 + j];
            acc2 += a * dw[2550 + j2];
        }
        out[cta * TILE + tid] = sigmf(acc2);
    }
}

extern "C" void kernel_launch(void* const* d_in, const int* in_sizes, int n_in,
                              void* d_out, int out_size) {
    cudaFuncSetAttribute(lstm_fused, cudaFuncAttributeMaxDynamicSharedMemorySize, SMEM_TOTAL);
    lstm_fused<<<NCTA, THREADS, SMEM_TOTAL>>>(
        (const float*)d_in[0],
        (const float*)d_in[1],  (const float*)d_in[2],  (const float*)d_in[3],
        (const float*)d_in[4],  (const float*)d_in[5],  (const float*)d_in[6],
        (const float*)d_in[7],  (const float*)d_in[8],  (const float*)d_in[9],
        (const float*)d_in[10], (const float*)d_in[11], (const float*)d_in[12],
        (const float*)d_in[13], (const float*)d_in[14],
        (const float*)d_in[15], (const float*)d_in[16],
        (float*)d_out);
}